// round 14
// baseline (speedup 1.0000x reference)
#include <cuda_runtime.h>
#include <math.h>

#define NB 20
#define NC 256
#define HW 4096
#define NCHUNK 10
#define QMAXF 255.0f
#define NPAIR (NB * NC / 2)

// ---------------- device scratch ----------------
__device__ float g_bc_min[NB * NC];
__device__ float g_bc_max[NB * NC];
__device__ float g_bc_sum[NB * NC];   // raw sum of x per (b,c)
__device__ float g_sq[3];             // [0]=s, [1]=zp, [2]=1/s
__device__ float g_sa[NC];            // out = q * sa[c] + b2[c]
__device__ float g_b2[NC];

__device__ __forceinline__ void pdl_wait() {
    asm volatile("griddepcontrol.wait;" ::: "memory");
}
__device__ __forceinline__ void pdl_launch_dependents() {
    asm volatile("griddepcontrol.launch_dependents;" ::: "memory");
}

// fast fake-quant core: clipped rounded quant level (integer-valued float in [0,255])
__device__ __forceinline__ float qlevel(float x, float rs, float zp) {
    float v = fmaf(x, rs, zp);
    v = fminf(fmaxf(v, 0.0f), QMAXF);
    return rintf(v);              // round-half-even == jnp.round
}

// -------- K1: warp-per-tile min/max/sum — no smem, no barriers, pure shuffles ----------
__global__ void __launch_bounds__(256) k_minmax(const float* __restrict__ x) {
    const int ln = threadIdx.x & 31;
    const int w  = threadIdx.x >> 5;
    const int bc = blockIdx.x * 8 + w;           // one (b,c) tile per warp
    const float4* p = reinterpret_cast<const float4*>(x) + (size_t)bc * (HW / 4);

    float mn = INFINITY, mx = -INFINITY, su = 0.f;
    #pragma unroll
    for (int b = 0; b < 4; b++) {
        float4 v[8];
        #pragma unroll
        for (int k = 0; k < 8; k++) v[k] = __ldcg(&p[ln + (b * 8 + k) * 32]);
        #pragma unroll
        for (int k = 0; k < 8; k++) {
            mn = fminf(mn, fminf(fminf(v[k].x, v[k].y), fminf(v[k].z, v[k].w)));
            mx = fmaxf(mx, fmaxf(fmaxf(v[k].x, v[k].y), fmaxf(v[k].z, v[k].w)));
            su += (v[k].x + v[k].y) + (v[k].z + v[k].w);
        }
    }
    #pragma unroll
    for (int o = 16; o > 0; o >>= 1) {
        mn = fminf(mn, __shfl_xor_sync(0xffffffffu, mn, o));
        mx = fmaxf(mx, __shfl_xor_sync(0xffffffffu, mx, o));
        su += __shfl_xor_sync(0xffffffffu, su, o);
    }
    if (ln == 0) {
        g_bc_min[bc] = mn; g_bc_max[bc] = mx; g_bc_sum[bc] = su;
    }
    pdl_launch_dependents();
}

// -------- K2: scalars, chunk ranges, weight/bias quant, final coefficients (1 block) ---
__global__ void k_stats(const float* __restrict__ w, const float* __restrict__ bias) {
    const int t = threadIdx.x;
    const int wr = t >> 5, ln = t & 31;
    __shared__ float sh_smin[NB], sh_smax[NB];
    __shared__ float sh_s, sh_zp, sh_rs, sh_wmin, sh_wmax, sh_bsum;

    // weight/bias loads are independent of k_minmax — issue before the PDL wait
    float wv = w[t], bv = bias[t];

    pdl_wait();   // all g_bc_* now visible

    // per-sample min/max over channels: warp wr handles samples wr, wr+8, wr+16
    for (int b = wr; b < NB; b += 8) {
        float mn = INFINITY, mx = -INFINITY;
        #pragma unroll
        for (int i = 0; i < NC / 32; i++) {
            mn = fminf(mn, g_bc_min[b * NC + i * 32 + ln]);
            mx = fmaxf(mx, g_bc_max[b * NC + i * 32 + ln]);
        }
        #pragma unroll
        for (int o = 16; o > 0; o >>= 1) {
            mn = fminf(mn, __shfl_xor_sync(0xffffffffu, mn, o));
            mx = fmaxf(mx, __shfl_xor_sync(0xffffffffu, mx, o));
        }
        if (ln == 0) { sh_smin[b] = mn; sh_smax[b] = mx; }
    }
    __syncthreads();
    if (t == 0) {
        float a = 0.f, b = 0.f;
        #pragma unroll
        for (int i = 0; i < NB; i++) { a += sh_smin[i]; b += sh_smax[i]; }
        float min_v = a / (float)NB, max_v = b / (float)NB;
        float s = (max_v - min_v) / QMAXF;
        if (s == 0.0f) s = 1.0f;
        float zp = truncf(fminf(fmaxf(__fdiv_rn(-min_v, s), 0.0f), QMAXF));
        float rs = __fdiv_rn(1.0f, s);
        sh_s = s; sh_zp = zp; sh_rs = rs;
        g_sq[0] = s; g_sq[1] = zp; g_sq[2] = rs;
    }
    __syncthreads();
    const float s = sh_s, zp = sh_zp, rs = sh_rs;

    // chunk ranges per channel (t = channel). chunk k = batches {2k,2k+1};
    // fq monotone -> chunk min/max of xq = fq(chunk min/max of raw x).
    float range_scale;
    {
        const float cst = (float)(0.5 * 0.35 * (1.0 + sqrt(M_PI * log(4.0)))
                                  / sqrt(2.0 * log(8192.0)));   // n = 8192
        float csum = 0.f;
        #pragma unroll
        for (int k = 0; k < NCHUNK; k++) {
            float mn = fminf(g_bc_min[(2 * k) * NC + t], g_bc_min[(2 * k + 1) * NC + t]);
            float mx = fmaxf(g_bc_max[(2 * k) * NC + t], g_bc_max[(2 * k + 1) * NC + t]);
            float fmx = (qlevel(mx, rs, zp) - zp) * s;
            float fmn = (qlevel(mn, rs, zp) - zp) * s;
            csum += (fmx - fmn) * cst;
        }
        range_scale = __fdiv_rn(1.0f, csum / (float)NCHUNK + 1e-7f);
    }

    // weight min/max + bias sum (256 elements, one per thread)
    float wmn = wv, wmx = wv, bs = bv;
    #pragma unroll
    for (int o = 16; o > 0; o >>= 1) {
        wmn = fminf(wmn, __shfl_xor_sync(0xffffffffu, wmn, o));
        wmx = fmaxf(wmx, __shfl_xor_sync(0xffffffffu, wmx, o));
        bs += __shfl_xor_sync(0xffffffffu, bs, o);
    }
    __shared__ float swmn[8], swmx[8], sbs[8];
    if (ln == 0) { swmn[wr] = wmn; swmx[wr] = wmx; sbs[wr] = bs; }
    __syncthreads();
    if (t == 0) {
        float a = swmn[0], b = swmx[0], c = sbs[0];
        #pragma unroll
        for (int i = 1; i < 8; i++) { a = fminf(a, swmn[i]); b = fmaxf(b, swmx[i]); c += sbs[i]; }
        sh_wmin = a; sh_wmax = b; sh_bsum = c;
    }
    __syncthreads();

    // quantized weight (explicit min/max)
    float ws = (sh_wmax - sh_wmin) / QMAXF;
    if (ws == 0.0f) ws = 1.0f;
    float wzp = truncf(fminf(fmaxf(__fdiv_rn(-sh_wmin, ws), 0.0f), QMAXF));
    float qw = (rintf(fminf(fmaxf(__fdiv_rn(wv, ws) + wzp, 0.0f), QMAXF)) - wzp) * ws;

    // quantized bias: min==max==bias.mean() -> scale=0 -> scale=1 branch
    float bmean = sh_bsum / (float)NC;
    float bzp = truncf(fminf(fmaxf(-bmean, 0.0f), QMAXF));
    float qb = rintf(fminf(fmaxf(bv + bzp, 0.0f), QMAXF)) - bzp;

    // channel mean of xq ~= channel mean of raw x (quant noise averages out over
    // 81920 elems: ~1e-4 rel_err contribution, budget 1e-3). t = channel.
    float acc = 0.f;
    #pragma unroll
    for (int bb = 0; bb < NB; bb++) acc += g_bc_sum[bb * NC + t] * (1.0f / (float)HW);
    float mean = acc * (1.0f / (float)NB);

    // out = ((q - zp)*s - mean)*a + qb = q*(s*a) + (qb - (mean + zp*s)*a)
    float a = range_scale * qw;
    g_sa[t] = s * a;
    g_b2[t] = fmaf(-(mean + zp * s), a, qb);
    pdl_launch_dependents();
}

// ------ K3: out = qlevel(x)*sa[c] + b2[c]; DESCENDING bc order to ride L2 LRU ----------
__global__ void __launch_bounds__(256) k_out(const float* __restrict__ x,
                                             float* __restrict__ out) {
    const int t = threadIdx.x;
    // reversed mapping: block 0 handles the hottest (most recently warmed) tiles
    const int bc0 = (NPAIR - 1 - blockIdx.x) * 2;
    const int c0 = bc0 & (NC - 1);              // tiles are same b, channels c0, c0+1

    const float4* pA = reinterpret_cast<const float4*>(x) + (size_t)bc0 * (HW / 4);
    const float4* pB = pA + (HW / 4);
    float4* poA = reinterpret_cast<float4*>(out) + (size_t)bc0 * (HW / 4);
    float4* poB = poA + (HW / 4);

    // x loads are independent of k_stats — prefetch first batch before the wait
    float4 a0 = __ldcg(&pA[t]);
    float4 b0 = __ldcg(&pB[t]);

    pdl_wait();   // coefficients now visible

    const float rs = g_sq[2], zp = g_sq[1];
    const float saA = g_sa[c0],     b2A = g_b2[c0];
    const float saB = g_sa[c0 + 1], b2B = g_b2[c0 + 1];

    float4 r;
    r.x = fmaf(qlevel(a0.x, rs, zp), saA, b2A);
    r.y = fmaf(qlevel(a0.y, rs, zp), saA, b2A);
    r.z = fmaf(qlevel(a0.z, rs, zp), saA, b2A);
    r.w = fmaf(qlevel(a0.w, rs, zp), saA, b2A);
    __stcs(&poA[t], r);
    r.x = fmaf(qlevel(b0.x, rs, zp), saB, b2B);
    r.y = fmaf(qlevel(b0.y, rs, zp), saB, b2B);
    r.z = fmaf(qlevel(b0.z, rs, zp), saB, b2B);
    r.w = fmaf(qlevel(b0.w, rs, zp), saB, b2B);
    __stcs(&poB[t], r);

    #pragma unroll
    for (int k = 1; k < 4; k++) {
        float4 a = __ldcg(&pA[t + k * 256]);
        float4 b = __ldcg(&pB[t + k * 256]);
        r.x = fmaf(qlevel(a.x, rs, zp), saA, b2A);
        r.y = fmaf(qlevel(a.y, rs, zp), saA, b2A);
        r.z = fmaf(qlevel(a.z, rs, zp), saA, b2A);
        r.w = fmaf(qlevel(a.w, rs, zp), saA, b2A);
        __stcs(&poA[t + k * 256], r);
        r.x = fmaf(qlevel(b.x, rs, zp), saB, b2B);
        r.y = fmaf(qlevel(b.y, rs, zp), saB, b2B);
        r.z = fmaf(qlevel(b.z, rs, zp), saB, b2B);
        r.w = fmaf(qlevel(b.w, rs, zp), saB, b2B);
        __stcs(&poB[t + k * 256], r);
    }
}

// ---------------- launch ----------------
extern "C" void kernel_launch(void* const* d_in, const int* in_sizes, int n_in,
                              void* d_out, int out_size) {
    const float* x    = (const float*)d_in[0];
    const float* w    = (const float*)d_in[1];
    const float* bias = (const float*)d_in[2];
    float* out = (float*)d_out;

    k_minmax<<<NB * NC / 8, 256>>>(x);

    cudaLaunchAttribute attr[1];
    attr[0].id = cudaLaunchAttributeProgrammaticStreamSerialization;
    attr[0].val.programmaticStreamSerializationAllowed = 1;

    {   // k_stats with PDL
        cudaLaunchConfig_t cfg = {};
        cfg.gridDim = dim3(1, 1, 1);
        cfg.blockDim = dim3(256, 1, 1);
        cfg.attrs = attr;
        cfg.numAttrs = 1;
        cudaLaunchKernelEx(&cfg, k_stats, w, bias);
    }
    {   // k_out with PDL
        cudaLaunchConfig_t cfg = {};
        cfg.gridDim = dim3(NPAIR, 1, 1);
        cfg.blockDim = dim3(256, 1, 1);
        cfg.attrs = attr;
        cfg.numAttrs = 1;
        cudaLaunchKernelEx(&cfg, k_out, x, out);
    }
}

// round 16
// speedup vs baseline: 1.0318x; 1.0318x over previous
#include <cuda_runtime.h>
#include <math.h>

#define NB 20
#define NC 256
#define HW 4096
#define NCHUNK 10
#define QMAXF 255.0f
#define NPAIR (NB * NC / 2)

// ---------------- device scratch ----------------
__device__ float g_bc_min[NB * NC];
__device__ float g_bc_max[NB * NC];
__device__ float g_bc_sum[NB * NC];   // raw sum of x per (b,c)
__device__ float g_sq[3];             // [0]=s, [1]=zp, [2]=1/s
__device__ float g_sa[NC];            // out = q * sa[c] + b2[c]
__device__ float g_b2[NC];

__device__ __forceinline__ void pdl_wait() {
    asm volatile("griddepcontrol.wait;" ::: "memory");
}
__device__ __forceinline__ void pdl_launch_dependents() {
    asm volatile("griddepcontrol.launch_dependents;" ::: "memory");
}

// fast fake-quant core: clipped rounded quant level (integer-valued float in [0,255])
__device__ __forceinline__ float qlevel(float x, float rs, float zp) {
    float v = fmaf(x, rs, zp);
    v = fminf(fmaxf(v, 0.0f), QMAXF);
    return rintf(v);              // round-half-even == jnp.round
}

// -------- K1: warp-per-tile min/max/sum — no smem, no barriers, pure shuffles ----------
// Launched WITH the PDL attribute: in graph replay it overlaps the previous
// iteration's k_out tail. No pdl_wait needed — inputs (x) are never written.
__global__ void __launch_bounds__(256) k_minmax(const float* __restrict__ x) {
    const int ln = threadIdx.x & 31;
    const int w  = threadIdx.x >> 5;
    const int bc = blockIdx.x * 8 + w;           // one (b,c) tile per warp
    const float4* p = reinterpret_cast<const float4*>(x) + (size_t)bc * (HW / 4);

    float mn = INFINITY, mx = -INFINITY, su = 0.f;
    #pragma unroll
    for (int b = 0; b < 4; b++) {
        float4 v[8];
        #pragma unroll
        for (int k = 0; k < 8; k++) v[k] = __ldcg(&p[ln + (b * 8 + k) * 32]);
        #pragma unroll
        for (int k = 0; k < 8; k++) {
            mn = fminf(mn, fminf(fminf(v[k].x, v[k].y), fminf(v[k].z, v[k].w)));
            mx = fmaxf(mx, fmaxf(fmaxf(v[k].x, v[k].y), fmaxf(v[k].z, v[k].w)));
            su += (v[k].x + v[k].y) + (v[k].z + v[k].w);
        }
    }
    #pragma unroll
    for (int o = 16; o > 0; o >>= 1) {
        mn = fminf(mn, __shfl_xor_sync(0xffffffffu, mn, o));
        mx = fmaxf(mx, __shfl_xor_sync(0xffffffffu, mx, o));
        su += __shfl_xor_sync(0xffffffffu, su, o);
    }
    if (ln == 0) {
        g_bc_min[bc] = mn; g_bc_max[bc] = mx; g_bc_sum[bc] = su;
    }
    pdl_launch_dependents();
}

// -------- K2: scalars, chunk ranges, weight/bias quant, final coefficients (1 block) ---
__global__ void k_stats(const float* __restrict__ w, const float* __restrict__ bias) {
    const int t = threadIdx.x;
    const int wr = t >> 5, ln = t & 31;
    __shared__ float sh_smin[NB], sh_smax[NB];
    __shared__ float sh_s, sh_zp, sh_rs, sh_wmin, sh_wmax, sh_bsum;

    // weight/bias loads are independent of k_minmax — issue before the PDL wait
    float wv = w[t], bv = bias[t];

    pdl_wait();   // all g_bc_* now visible

    // per-sample min/max over channels: warp wr handles samples wr, wr+8, wr+16
    for (int b = wr; b < NB; b += 8) {
        float mn = INFINITY, mx = -INFINITY;
        #pragma unroll
        for (int i = 0; i < NC / 32; i++) {
            mn = fminf(mn, g_bc_min[b * NC + i * 32 + ln]);
            mx = fmaxf(mx, g_bc_max[b * NC + i * 32 + ln]);
        }
        #pragma unroll
        for (int o = 16; o > 0; o >>= 1) {
            mn = fminf(mn, __shfl_xor_sync(0xffffffffu, mn, o));
            mx = fmaxf(mx, __shfl_xor_sync(0xffffffffu, mx, o));
        }
        if (ln == 0) { sh_smin[b] = mn; sh_smax[b] = mx; }
    }
    __syncthreads();
    if (t == 0) {
        float a = 0.f, b = 0.f;
        #pragma unroll
        for (int i = 0; i < NB; i++) { a += sh_smin[i]; b += sh_smax[i]; }
        float min_v = a / (float)NB, max_v = b / (float)NB;
        float s = (max_v - min_v) / QMAXF;
        if (s == 0.0f) s = 1.0f;
        float zp = truncf(fminf(fmaxf(__fdiv_rn(-min_v, s), 0.0f), QMAXF));
        float rs = __fdiv_rn(1.0f, s);
        sh_s = s; sh_zp = zp; sh_rs = rs;
        g_sq[0] = s; g_sq[1] = zp; g_sq[2] = rs;
    }
    __syncthreads();
    const float s = sh_s, zp = sh_zp, rs = sh_rs;

    // chunk ranges per channel (t = channel). chunk k = batches {2k,2k+1};
    // fq monotone -> chunk min/max of xq = fq(chunk min/max of raw x).
    float range_scale;
    {
        const float cst = (float)(0.5 * 0.35 * (1.0 + sqrt(M_PI * log(4.0)))
                                  / sqrt(2.0 * log(8192.0)));   // n = 8192
        float csum = 0.f;
        #pragma unroll
        for (int k = 0; k < NCHUNK; k++) {
            float mn = fminf(g_bc_min[(2 * k) * NC + t], g_bc_min[(2 * k + 1) * NC + t]);
            float mx = fmaxf(g_bc_max[(2 * k) * NC + t], g_bc_max[(2 * k + 1) * NC + t]);
            float fmx = (qlevel(mx, rs, zp) - zp) * s;
            float fmn = (qlevel(mn, rs, zp) - zp) * s;
            csum += (fmx - fmn) * cst;
        }
        range_scale = __fdiv_rn(1.0f, csum / (float)NCHUNK + 1e-7f);
    }

    // weight min/max + bias sum (256 elements, one per thread)
    float wmn = wv, wmx = wv, bs = bv;
    #pragma unroll
    for (int o = 16; o > 0; o >>= 1) {
        wmn = fminf(wmn, __shfl_xor_sync(0xffffffffu, wmn, o));
        wmx = fmaxf(wmx, __shfl_xor_sync(0xffffffffu, wmx, o));
        bs += __shfl_xor_sync(0xffffffffu, bs, o);
    }
    __shared__ float swmn[8], swmx[8], sbs[8];
    if (ln == 0) { swmn[wr] = wmn; swmx[wr] = wmx; sbs[wr] = bs; }
    __syncthreads();
    if (t == 0) {
        float a = swmn[0], b = swmx[0], c = sbs[0];
        #pragma unroll
        for (int i = 1; i < 8; i++) { a = fminf(a, swmn[i]); b = fmaxf(b, swmx[i]); c += sbs[i]; }
        sh_wmin = a; sh_wmax = b; sh_bsum = c;
    }
    __syncthreads();

    // quantized weight (explicit min/max)
    float ws = (sh_wmax - sh_wmin) / QMAXF;
    if (ws == 0.0f) ws = 1.0f;
    float wzp = truncf(fminf(fmaxf(__fdiv_rn(-sh_wmin, ws), 0.0f), QMAXF));
    float qw = (rintf(fminf(fmaxf(__fdiv_rn(wv, ws) + wzp, 0.0f), QMAXF)) - wzp) * ws;

    // quantized bias: min==max==bias.mean() -> scale=0 -> scale=1 branch
    float bmean = sh_bsum / (float)NC;
    float bzp = truncf(fminf(fmaxf(-bmean, 0.0f), QMAXF));
    float qb = rintf(fminf(fmaxf(bv + bzp, 0.0f), QMAXF)) - bzp;

    // channel mean of xq ~= channel mean of raw x (quant noise averages out over
    // 81920 elems: ~1e-4 rel_err contribution, budget 1e-3). t = channel.
    float acc = 0.f;
    #pragma unroll
    for (int bb = 0; bb < NB; bb++) acc += g_bc_sum[bb * NC + t] * (1.0f / (float)HW);
    float mean = acc * (1.0f / (float)NB);

    // out = ((q - zp)*s - mean)*a + qb = q*(s*a) + (qb - (mean + zp*s)*a)
    float a = range_scale * qw;
    g_sa[t] = s * a;
    g_b2[t] = fmaf(-(mean + zp * s), a, qb);
    pdl_launch_dependents();
}

// ---------------- K3: out = qlevel(x)*sa[c] + b2[c], 2 tiles/block (R12 best) ----------
// Ends with pdl_launch_dependents so next graph-replay iteration's k_minmax
// (which has no data dependence on out) can ramp under our store drain.
__global__ void __launch_bounds__(256) k_out(const float* __restrict__ x,
                                             float* __restrict__ out) {
    const int t = threadIdx.x;
    const int bc0 = blockIdx.x * 2;
    const int c0 = bc0 & (NC - 1);              // tiles are same b, channels c0, c0+1

    const float4* pA = reinterpret_cast<const float4*>(x) + (size_t)bc0 * (HW / 4);
    const float4* pB = pA + (HW / 4);
    float4* poA = reinterpret_cast<float4*>(out) + (size_t)bc0 * (HW / 4);
    float4* poB = poA + (HW / 4);

    // x loads are independent of k_stats — prefetch first batch before the wait
    float4 a0 = pA[t];
    float4 b0 = pB[t];

    pdl_wait();   // coefficients now visible

    const float rs = g_sq[2], zp = g_sq[1];
    const float saA = g_sa[c0],     b2A = g_b2[c0];
    const float saB = g_sa[c0 + 1], b2B = g_b2[c0 + 1];

    float4 r;
    r.x = fmaf(qlevel(a0.x, rs, zp), saA, b2A);
    r.y = fmaf(qlevel(a0.y, rs, zp), saA, b2A);
    r.z = fmaf(qlevel(a0.z, rs, zp), saA, b2A);
    r.w = fmaf(qlevel(a0.w, rs, zp), saA, b2A);
    __stcs(&poA[t], r);
    r.x = fmaf(qlevel(b0.x, rs, zp), saB, b2B);
    r.y = fmaf(qlevel(b0.y, rs, zp), saB, b2B);
    r.z = fmaf(qlevel(b0.z, rs, zp), saB, b2B);
    r.w = fmaf(qlevel(b0.w, rs, zp), saB, b2B);
    __stcs(&poB[t], r);

    #pragma unroll
    for (int k = 1; k < 4; k++) {
        float4 a = pA[t + k * 256];
        float4 b = pB[t + k * 256];
        r.x = fmaf(qlevel(a.x, rs, zp), saA, b2A);
        r.y = fmaf(qlevel(a.y, rs, zp), saA, b2A);
        r.z = fmaf(qlevel(a.z, rs, zp), saA, b2A);
        r.w = fmaf(qlevel(a.w, rs, zp), saA, b2A);
        __stcs(&poA[t + k * 256], r);
        r.x = fmaf(qlevel(b.x, rs, zp), saB, b2B);
        r.y = fmaf(qlevel(b.y, rs, zp), saB, b2B);
        r.z = fmaf(qlevel(b.z, rs, zp), saB, b2B);
        r.w = fmaf(qlevel(b.w, rs, zp), saB, b2B);
        __stcs(&poB[t + k * 256], r);
    }
    pdl_launch_dependents();   // let next iteration's k_minmax overlap our tail
}

// ---------------- launch ----------------
extern "C" void kernel_launch(void* const* d_in, const int* in_sizes, int n_in,
                              void* d_out, int out_size) {
    const float* x    = (const float*)d_in[0];
    const float* w    = (const float*)d_in[1];
    const float* bias = (const float*)d_in[2];
    float* out = (float*)d_out;

    cudaLaunchAttribute attr[1];
    attr[0].id = cudaLaunchAttributeProgrammaticStreamSerialization;
    attr[0].val.programmaticStreamSerializationAllowed = 1;

    {   // k_minmax with PDL: overlaps previous replay iteration's k_out tail
        cudaLaunchConfig_t cfg = {};
        cfg.gridDim = dim3(NB * NC / 8, 1, 1);
        cfg.blockDim = dim3(256, 1, 1);
        cfg.attrs = attr;
        cfg.numAttrs = 1;
        cudaLaunchKernelEx(&cfg, k_minmax, x);
    }
    {   // k_stats with PDL
        cudaLaunchConfig_t cfg = {};
        cfg.gridDim = dim3(1, 1, 1);
        cfg.blockDim = dim3(256, 1, 1);
        cfg.attrs = attr;
        cfg.numAttrs = 1;
        cudaLaunchKernelEx(&cfg, k_stats, w, bias);
    }
    {   // k_out with PDL
        cudaLaunchConfig_t cfg = {};
        cfg.gridDim = dim3(NPAIR, 1, 1);
        cfg.blockDim = dim3(256, 1, 1);
        cfg.attrs = attr;
        cfg.numAttrs = 1;
        cudaLaunchKernelEx(&cfg, k_out, x, out);
    }
}

// round 17
// speedup vs baseline: 1.0394x; 1.0074x over previous
#include <cuda_runtime.h>
#include <math.h>

#define NB 20
#define NC 256
#define HW 4096
#define NCHUNK 10
#define QMAXF 255.0f
#define NPAIR (NB * NC / 2)

// ---------------- device scratch ----------------
__device__ float g_bc_min[NB * NC];
__device__ float g_bc_max[NB * NC];
__device__ float g_bc_sum[NB * NC];   // raw sum of x per (b,c)
__device__ float g_sq[3];             // [0]=s, [1]=zp, [2]=1/s
__device__ float g_sa[NC];            // out = q * sa[c] + b2[c]
__device__ float g_b2[NC];

__device__ __forceinline__ void pdl_wait() {
    asm volatile("griddepcontrol.wait;" ::: "memory");
}
__device__ __forceinline__ void pdl_launch_dependents() {
    asm volatile("griddepcontrol.launch_dependents;" ::: "memory");
}

// fast fake-quant core: clipped rounded quant level (integer-valued float in [0,255])
__device__ __forceinline__ float qlevel(float x, float rs, float zp) {
    float v = fmaf(x, rs, zp);
    v = fminf(fmaxf(v, 0.0f), QMAXF);
    return rintf(v);              // round-half-even == jnp.round
}

// -------- K1: warp-per-tile min/max/sum; 128-thr blocks for fine drain granularity -----
__global__ void __launch_bounds__(128) k_minmax(const float* __restrict__ x) {
    const int ln = threadIdx.x & 31;
    const int w  = threadIdx.x >> 5;
    const int bc = blockIdx.x * 4 + w;           // one (b,c) tile per warp
    const float4* p = reinterpret_cast<const float4*>(x) + (size_t)bc * (HW / 4);

    float mn = INFINITY, mx = -INFINITY, su = 0.f;
    #pragma unroll
    for (int b = 0; b < 4; b++) {
        float4 v[8];
        #pragma unroll
        for (int k = 0; k < 8; k++) v[k] = __ldcg(&p[ln + (b * 8 + k) * 32]);
        #pragma unroll
        for (int k = 0; k < 8; k++) {
            mn = fminf(mn, fminf(fminf(v[k].x, v[k].y), fminf(v[k].z, v[k].w)));
            mx = fmaxf(mx, fmaxf(fmaxf(v[k].x, v[k].y), fmaxf(v[k].z, v[k].w)));
            su += (v[k].x + v[k].y) + (v[k].z + v[k].w);
        }
    }
    #pragma unroll
    for (int o = 16; o > 0; o >>= 1) {
        mn = fminf(mn, __shfl_xor_sync(0xffffffffu, mn, o));
        mx = fmaxf(mx, __shfl_xor_sync(0xffffffffu, mx, o));
        su += __shfl_xor_sync(0xffffffffu, su, o);
    }
    if (ln == 0) {
        g_bc_min[bc] = mn; g_bc_max[bc] = mx; g_bc_sum[bc] = su;
    }
    pdl_launch_dependents();
}

// -------- K2: scalars, chunk ranges, weight/bias quant, final coefficients (1 block) ---
__global__ void k_stats(const float* __restrict__ w, const float* __restrict__ bias) {
    const int t = threadIdx.x;
    const int wr = t >> 5, ln = t & 31;
    __shared__ float sh_smin[NB], sh_smax[NB];
    __shared__ float sh_s, sh_zp, sh_rs, sh_wmin, sh_wmax, sh_bsum;

    // weight/bias loads are independent of k_minmax — issue before the PDL wait
    float wv = w[t], bv = bias[t];

    pdl_wait();   // all g_bc_* now visible

    // per-sample min/max over channels: warp wr handles samples wr, wr+8, wr+16
    for (int b = wr; b < NB; b += 8) {
        float mn = INFINITY, mx = -INFINITY;
        #pragma unroll
        for (int i = 0; i < NC / 32; i++) {
            mn = fminf(mn, g_bc_min[b * NC + i * 32 + ln]);
            mx = fmaxf(mx, g_bc_max[b * NC + i * 32 + ln]);
        }
        #pragma unroll
        for (int o = 16; o > 0; o >>= 1) {
            mn = fminf(mn, __shfl_xor_sync(0xffffffffu, mn, o));
            mx = fmaxf(mx, __shfl_xor_sync(0xffffffffu, mx, o));
        }
        if (ln == 0) { sh_smin[b] = mn; sh_smax[b] = mx; }
    }
    __syncthreads();
    if (t == 0) {
        float a = 0.f, b = 0.f;
        #pragma unroll
        for (int i = 0; i < NB; i++) { a += sh_smin[i]; b += sh_smax[i]; }
        float min_v = a / (float)NB, max_v = b / (float)NB;
        float s = (max_v - min_v) / QMAXF;
        if (s == 0.0f) s = 1.0f;
        float zp = truncf(fminf(fmaxf(__fdiv_rn(-min_v, s), 0.0f), QMAXF));
        float rs = __fdiv_rn(1.0f, s);
        sh_s = s; sh_zp = zp; sh_rs = rs;
        g_sq[0] = s; g_sq[1] = zp; g_sq[2] = rs;
    }
    __syncthreads();
    const float s = sh_s, zp = sh_zp, rs = sh_rs;

    // chunk ranges per channel (t = channel). chunk k = batches {2k,2k+1};
    // fq monotone -> chunk min/max of xq = fq(chunk min/max of raw x).
    float range_scale;
    {
        const float cst = (float)(0.5 * 0.35 * (1.0 + sqrt(M_PI * log(4.0)))
                                  / sqrt(2.0 * log(8192.0)));   // n = 8192
        float csum = 0.f;
        #pragma unroll
        for (int k = 0; k < NCHUNK; k++) {
            float mn = fminf(g_bc_min[(2 * k) * NC + t], g_bc_min[(2 * k + 1) * NC + t]);
            float mx = fmaxf(g_bc_max[(2 * k) * NC + t], g_bc_max[(2 * k + 1) * NC + t]);
            float fmx = (qlevel(mx, rs, zp) - zp) * s;
            float fmn = (qlevel(mn, rs, zp) - zp) * s;
            csum += (fmx - fmn) * cst;
        }
        range_scale = __fdiv_rn(1.0f, csum / (float)NCHUNK + 1e-7f);
    }

    // weight min/max + bias sum (256 elements, one per thread)
    float wmn = wv, wmx = wv, bs = bv;
    #pragma unroll
    for (int o = 16; o > 0; o >>= 1) {
        wmn = fminf(wmn, __shfl_xor_sync(0xffffffffu, wmn, o));
        wmx = fmaxf(wmx, __shfl_xor_sync(0xffffffffu, wmx, o));
        bs += __shfl_xor_sync(0xffffffffu, bs, o);
    }
    __shared__ float swmn[8], swmx[8], sbs[8];
    if (ln == 0) { swmn[wr] = wmn; swmx[wr] = wmx; sbs[wr] = bs; }
    __syncthreads();
    if (t == 0) {
        float a = swmn[0], b = swmx[0], c = sbs[0];
        #pragma unroll
        for (int i = 1; i < 8; i++) { a = fminf(a, swmn[i]); b = fmaxf(b, swmx[i]); c += sbs[i]; }
        sh_wmin = a; sh_wmax = b; sh_bsum = c;
    }
    __syncthreads();

    // quantized weight (explicit min/max)
    float ws = (sh_wmax - sh_wmin) / QMAXF;
    if (ws == 0.0f) ws = 1.0f;
    float wzp = truncf(fminf(fmaxf(__fdiv_rn(-sh_wmin, ws), 0.0f), QMAXF));
    float qw = (rintf(fminf(fmaxf(__fdiv_rn(wv, ws) + wzp, 0.0f), QMAXF)) - wzp) * ws;

    // quantized bias: min==max==bias.mean() -> scale=0 -> scale=1 branch
    float bmean = sh_bsum / (float)NC;
    float bzp = truncf(fminf(fmaxf(-bmean, 0.0f), QMAXF));
    float qb = rintf(fminf(fmaxf(bv + bzp, 0.0f), QMAXF)) - bzp;

    // channel mean of xq ~= channel mean of raw x (quant noise averages out over
    // 81920 elems: ~1e-4 rel_err contribution, budget 1e-3). t = channel.
    float acc = 0.f;
    #pragma unroll
    for (int bb = 0; bb < NB; bb++) acc += g_bc_sum[bb * NC + t] * (1.0f / (float)HW);
    float mean = acc * (1.0f / (float)NB);

    // out = ((q - zp)*s - mean)*a + qb = q*(s*a) + (qb - (mean + zp*s)*a)
    float a = range_scale * qw;
    g_sa[t] = s * a;
    g_b2[t] = fmaf(-(mean + zp * s), a, qb);
    pdl_launch_dependents();
}

// ---------------- K3: out = qlevel(x)*sa[c] + b2[c], 2 tiles/block (R12 best) ----------
__global__ void __launch_bounds__(256) k_out(const float* __restrict__ x,
                                             float* __restrict__ out) {
    const int t = threadIdx.x;
    const int bc0 = blockIdx.x * 2;
    const int c0 = bc0 & (NC - 1);              // tiles are same b, channels c0, c0+1

    const float4* pA = reinterpret_cast<const float4*>(x) + (size_t)bc0 * (HW / 4);
    const float4* pB = pA + (HW / 4);
    float4* poA = reinterpret_cast<float4*>(out) + (size_t)bc0 * (HW / 4);
    float4* poB = poA + (HW / 4);

    // x loads are independent of k_stats — prefetch first batch before the wait
    float4 a0 = pA[t];
    float4 b0 = pB[t];

    pdl_wait();   // coefficients now visible

    const float rs = g_sq[2], zp = g_sq[1];
    const float saA = g_sa[c0],     b2A = g_b2[c0];
    const float saB = g_sa[c0 + 1], b2B = g_b2[c0 + 1];

    float4 r;
    r.x = fmaf(qlevel(a0.x, rs, zp), saA, b2A);
    r.y = fmaf(qlevel(a0.y, rs, zp), saA, b2A);
    r.z = fmaf(qlevel(a0.z, rs, zp), saA, b2A);
    r.w = fmaf(qlevel(a0.w, rs, zp), saA, b2A);
    __stcs(&poA[t], r);
    r.x = fmaf(qlevel(b0.x, rs, zp), saB, b2B);
    r.y = fmaf(qlevel(b0.y, rs, zp), saB, b2B);
    r.z = fmaf(qlevel(b0.z, rs, zp), saB, b2B);
    r.w = fmaf(qlevel(b0.w, rs, zp), saB, b2B);
    __stcs(&poB[t], r);

    #pragma unroll
    for (int k = 1; k < 4; k++) {
        float4 a = pA[t + k * 256];
        float4 b = pB[t + k * 256];
        r.x = fmaf(qlevel(a.x, rs, zp), saA, b2A);
        r.y = fmaf(qlevel(a.y, rs, zp), saA, b2A);
        r.z = fmaf(qlevel(a.z, rs, zp), saA, b2A);
        r.w = fmaf(qlevel(a.w, rs, zp), saA, b2A);
        __stcs(&poA[t + k * 256], r);
        r.x = fmaf(qlevel(b.x, rs, zp), saB, b2B);
        r.y = fmaf(qlevel(b.y, rs, zp), saB, b2B);
        r.z = fmaf(qlevel(b.z, rs, zp), saB, b2B);
        r.w = fmaf(qlevel(b.w, rs, zp), saB, b2B);
        __stcs(&poB[t + k * 256], r);
    }
    pdl_launch_dependents();   // let next iteration's k_minmax overlap our tail
}

// ---------------- launch ----------------
extern "C" void kernel_launch(void* const* d_in, const int* in_sizes, int n_in,
                              void* d_out, int out_size) {
    const float* x    = (const float*)d_in[0];
    const float* w    = (const float*)d_in[1];
    const float* bias = (const float*)d_in[2];
    float* out = (float*)d_out;

    cudaLaunchAttribute attr[1];
    attr[0].id = cudaLaunchAttributeProgrammaticStreamSerialization;
    attr[0].val.programmaticStreamSerializationAllowed = 1;

    {   // k_minmax with PDL: overlaps previous replay iteration's k_out tail
        cudaLaunchConfig_t cfg = {};
        cfg.gridDim = dim3(NB * NC / 4, 1, 1);   // 1280 blocks x 128 threads
        cfg.blockDim = dim3(128, 1, 1);
        cfg.attrs = attr;
        cfg.numAttrs = 1;
        cudaLaunchKernelEx(&cfg, k_minmax, x);
    }
    {   // k_stats with PDL
        cudaLaunchConfig_t cfg = {};
        cfg.gridDim = dim3(1, 1, 1);
        cfg.blockDim = dim3(256, 1, 1);
        cfg.attrs = attr;
        cfg.numAttrs = 1;
        cudaLaunchKernelEx(&cfg, k_stats, w, bias);
    }
    {   // k_out with PDL
        cudaLaunchConfig_t cfg = {};
        cfg.gridDim = dim3(NPAIR, 1, 1);
        cfg.blockDim = dim3(256, 1, 1);
        cfg.attrs = attr;
        cfg.numAttrs = 1;
        cudaLaunchKernelEx(&cfg, k_out, x, out);
    }
}